// round 1
// baseline (speedup 1.0000x reference)
#include <cuda_runtime.h>
#include <math.h>

#define BSZ  128
#define NDIM 256
#define HDIM 1024

#define ALPHA 60.0f
#define BETA  20.0f
#define EPSC  1e-8f

// ---- scratch (allocation-free: __device__ globals) ----
__device__ float g_Hf[BSZ * HDIM];
__device__ float g_Hg[BSZ * HDIM];
__device__ float g_Hk[BSZ * HDIM];
__device__ float g_D [BSZ * HDIM];
__device__ float g_f [BSZ * NDIM];
__device__ float g_g [BSZ * NDIM];
__device__ float g_k [BSZ * NDIM];
__device__ float g_dvf[BSZ * HDIM];
__device__ float g_dvg[BSZ * HDIM];
__device__ float g_Jf[BSZ * NDIM];
__device__ float g_JG[BSZ * NDIM];

// ============================================================
// Core tile GEMM: 64x64 output tile, BK=16, 256 threads, 4x4/thread.
// BT=true : C[m,n] = sum_k A[m*lda+k] * B[n*ldb+k]   (NT, both K-major)
// BT=false: C[m,n] = sum_k A[m*lda+k] * B[k*ldb+n]   (NN, B row-major [K,Nout])
// ============================================================
template <bool BT>
__device__ __forceinline__ void gemm_tile_64(
    const float* __restrict__ A, int lda,
    const float* __restrict__ B, int ldb,
    int K, int bm, int bn, float acc[4][4])
{
    constexpr int BK = 16;
    __shared__ float As[BK][64];
    __shared__ float Bs[BK][64];

    const int tid = threadIdx.x;
    const int tm = (tid >> 4) * 4;   // 0..60 step 4
    const int tn = (tid & 15) * 4;   // 0..60 step 4
    const int lr = tid >> 2;         // 0..63  (row for K-major loads)
    const int lc = (tid & 3) * 4;    // 0,4,8,12 (k offset)
    const int br = tid >> 4;         // 0..15  (k row for NN B load)
    const int bc = (tid & 15) * 4;   // 0..60  (n offset)

    for (int k0 = 0; k0 < K; k0 += BK) {
        float4 av = *reinterpret_cast<const float4*>(&A[(size_t)(bm + lr) * lda + k0 + lc]);
        As[lc + 0][lr] = av.x;
        As[lc + 1][lr] = av.y;
        As[lc + 2][lr] = av.z;
        As[lc + 3][lr] = av.w;
        if (BT) {
            float4 bv = *reinterpret_cast<const float4*>(&B[(size_t)(bn + lr) * ldb + k0 + lc]);
            Bs[lc + 0][lr] = bv.x;
            Bs[lc + 1][lr] = bv.y;
            Bs[lc + 2][lr] = bv.z;
            Bs[lc + 3][lr] = bv.w;
        } else {
            float4 bv = *reinterpret_cast<const float4*>(&B[(size_t)(k0 + br) * ldb + bn + bc]);
            *reinterpret_cast<float4*>(&Bs[br][bc]) = bv;
        }
        __syncthreads();
#pragma unroll
        for (int kk = 0; kk < BK; kk++) {
            float4 a4 = *reinterpret_cast<const float4*>(&As[kk][tm]);
            float4 b4 = *reinterpret_cast<const float4*>(&Bs[kk][tn]);
            float aa[4] = {a4.x, a4.y, a4.z, a4.w};
            float bb[4] = {b4.x, b4.y, b4.z, b4.w};
#pragma unroll
            for (int i = 0; i < 4; i++)
#pragma unroll
                for (int j = 0; j < 4; j++)
                    acc[i][j] = fmaf(aa[i], bb[j], acc[i][j]);
        }
        __syncthreads();
    }
}

// ============================================================
// Stage 1: H{f,g,k} = tanh(x @ W1^T + b1);  also D = 1 - Hk^2
// grid (HDIM/64=16, BSZ/64=2, 3), 256 threads
// ============================================================
__global__ void stage1_kernel(const float* __restrict__ x,
                              const float* __restrict__ Wf1, const float* __restrict__ bf1,
                              const float* __restrict__ Wg1, const float* __restrict__ bg1,
                              const float* __restrict__ Wk1, const float* __restrict__ bk1)
{
    const int z = blockIdx.z;
    const float* W    = (z == 0) ? Wf1 : (z == 1) ? Wg1 : Wk1;
    const float* bias = (z == 0) ? bf1 : (z == 1) ? bg1 : bk1;
    float* out        = (z == 0) ? g_Hf : (z == 1) ? g_Hg : g_Hk;

    const int bm = blockIdx.y * 64;
    const int bn = blockIdx.x * 64;
    float acc[4][4] = {};
    gemm_tile_64<true>(x, NDIM, W, NDIM, NDIM, bm, bn, acc);

    const int tid = threadIdx.x;
    const int tm = (tid >> 4) * 4, tn = (tid & 15) * 4;
#pragma unroll
    for (int i = 0; i < 4; i++) {
        const int row = bm + tm + i;
#pragma unroll
        for (int j = 0; j < 4; j++) {
            const int col = bn + tn + j;
            float t = tanhf(acc[i][j] + bias[col]);
            out[row * HDIM + col] = t;
            if (z == 2) g_D[row * HDIM + col] = 1.0f - t * t;
        }
    }
}

// ============================================================
// Stage 2: {f,g,k} = H{f,g,k} @ W2^T + b2
// grid (NDIM/64=4, 2, 3)
// ============================================================
__global__ void stage2_kernel(const float* __restrict__ Wf2, const float* __restrict__ bf2,
                              const float* __restrict__ Wg2, const float* __restrict__ bg2,
                              const float* __restrict__ Wk2, const float* __restrict__ bk2)
{
    const int z = blockIdx.z;
    const float* A    = (z == 0) ? g_Hf : (z == 1) ? g_Hg : g_Hk;
    const float* W    = (z == 0) ? Wf2 : (z == 1) ? Wg2 : Wk2;
    const float* bias = (z == 0) ? bf2 : (z == 1) ? bg2 : bk2;
    float* out        = (z == 0) ? g_f : (z == 1) ? g_g : g_k;

    const int bm = blockIdx.y * 64;
    const int bn = blockIdx.x * 64;
    float acc[4][4] = {};
    gemm_tile_64<true>(A, HDIM, W, HDIM, HDIM, bm, bn, acc);

    const int tid = threadIdx.x;
    const int tm = (tid >> 4) * 4, tn = (tid & 15) * 4;
#pragma unroll
    for (int i = 0; i < 4; i++) {
        const int row = bm + tm + i;
#pragma unroll
        for (int j = 0; j < 4; j++) {
            const int col = bn + tn + j;
            out[row * NDIM + col] = acc[i][j] + bias[col];
        }
    }
}

// ============================================================
// Stage 3: dv{f,g}[b,m] = D[b,m] * sum_i {f,g}[b,i] * Wk2[i,m]   (NN GEMM)
// grid (HDIM/64=16, 2, 2)
// ============================================================
__global__ void stage3_kernel(const float* __restrict__ Wk2)
{
    const int z = blockIdx.z;
    const float* A = (z == 0) ? g_f : g_g;
    float* out     = (z == 0) ? g_dvf : g_dvg;

    const int bm = blockIdx.y * 64;
    const int bn = blockIdx.x * 64;
    float acc[4][4] = {};
    gemm_tile_64<false>(A, NDIM, Wk2, HDIM, NDIM, bm, bn, acc);

    const int tid = threadIdx.x;
    const int tm = (tid >> 4) * 4, tn = (tid & 15) * 4;
#pragma unroll
    for (int i = 0; i < 4; i++) {
        const int row = bm + tm + i;
#pragma unroll
        for (int j = 0; j < 4; j++) {
            const int col = bn + tn + j;
            out[row * HDIM + col] = acc[i][j] * g_D[row * HDIM + col];
        }
    }
}

// ============================================================
// Stage 4: J{f,G}[b,j] = sum_m dv{f,g}[b,m] * Wk1[m,j]   (NN GEMM)
// grid (NDIM/64=4, 2, 2)
// ============================================================
__global__ void stage4_kernel(const float* __restrict__ Wk1)
{
    const int z = blockIdx.z;
    const float* A = (z == 0) ? g_dvf : g_dvg;
    float* out     = (z == 0) ? g_Jf : g_JG;

    const int bm = blockIdx.y * 64;
    const int bn = blockIdx.x * 64;
    float acc[4][4] = {};
    gemm_tile_64<false>(A, HDIM, Wk1, NDIM, HDIM, bm, bn, acc);

    const int tid = threadIdx.x;
    const int tm = (tid >> 4) * 4, tn = (tid & 15) * 4;
#pragma unroll
    for (int i = 0; i < 4; i++) {
        const int row = bm + tm + i;
#pragma unroll
        for (int j = 0; j < 4; j++) {
            const int col = bn + tn + j;
            out[row * NDIM + col] = acc[i][j];
        }
    }
}

// ============================================================
// Stage 5: per-row norms + mask + output. 1 block/row, 256 threads.
// mask = (||Jf|| - ALPHA*kn^9 > EPS) || (<k,JG> - BETA*kn^10 < -EPS)
// out = (mask ? 0.5 : 1.0) * (f + g)
// ============================================================
__global__ void stage5_kernel(float* __restrict__ out)
{
    const int b = blockIdx.x;
    const int i = threadIdx.x;  // 0..255
    const int idx = b * NDIM + i;

    const float kv  = g_k[idx];
    const float jfv = g_Jf[idx];
    const float jgv = g_JG[idx];

    float kn2 = kv * kv;
    float jf2 = jfv * jfv;
    float dt  = kv * jgv;

#pragma unroll
    for (int off = 16; off > 0; off >>= 1) {
        kn2 += __shfl_down_sync(0xffffffffu, kn2, off);
        jf2 += __shfl_down_sync(0xffffffffu, jf2, off);
        dt  += __shfl_down_sync(0xffffffffu, dt,  off);
    }

    __shared__ float s_kn2[8], s_jf2[8], s_dt[8];
    __shared__ float s_scale;
    const int warp = i >> 5, lane = i & 31;
    if (lane == 0) { s_kn2[warp] = kn2; s_jf2[warp] = jf2; s_dt[warp] = dt; }
    __syncthreads();

    if (i == 0) {
        float tkn2 = 0.f, tjf2 = 0.f, tdt = 0.f;
#pragma unroll
        for (int w = 0; w < 8; w++) { tkn2 += s_kn2[w]; tjf2 += s_jf2[w]; tdt += s_dt[w]; }
        float kn  = sqrtf(tkn2);
        float kn9 = tkn2 * tkn2 * tkn2 * tkn2 * kn;   // kn^9
        float kn10 = kn9 * kn;                         // kn^10
        float c1 = sqrtf(tjf2) - ALPHA * kn9;
        float c2 = tdt - BETA * kn10;
        bool mask = (c1 > EPSC) || (c2 < -EPSC);
        s_scale = mask ? 0.5f : 1.0f;
    }
    __syncthreads();

    out[idx] = s_scale * (g_f[idx] + g_g[idx]);
}

// ============================================================
// Launch: inputs in metadata order:
// 0:t 1:x 2:Wf1 3:bf1 4:Wf2 5:bf2 6:Wg1 7:bg1 8:Wg2 9:bg2 10:Wk1 11:bk1 12:Wk2 13:bk2
// ============================================================
extern "C" void kernel_launch(void* const* d_in, const int* in_sizes, int n_in,
                              void* d_out, int out_size)
{
    const float* x   = (const float*)d_in[1];
    const float* Wf1 = (const float*)d_in[2];
    const float* bf1 = (const float*)d_in[3];
    const float* Wf2 = (const float*)d_in[4];
    const float* bf2 = (const float*)d_in[5];
    const float* Wg1 = (const float*)d_in[6];
    const float* bg1 = (const float*)d_in[7];
    const float* Wg2 = (const float*)d_in[8];
    const float* bg2 = (const float*)d_in[9];
    const float* Wk1 = (const float*)d_in[10];
    const float* bk1 = (const float*)d_in[11];
    const float* Wk2 = (const float*)d_in[12];
    const float* bk2 = (const float*)d_in[13];
    float* out = (float*)d_out;

    dim3 blk(256);
    stage1_kernel<<<dim3(HDIM / 64, BSZ / 64, 3), blk>>>(x, Wf1, bf1, Wg1, bg1, Wk1, bk1);
    stage2_kernel<<<dim3(NDIM / 64, BSZ / 64, 3), blk>>>(Wf2, bf2, Wg2, bg2, Wk2, bk2);
    stage3_kernel<<<dim3(HDIM / 64, BSZ / 64, 2), blk>>>(Wk2);
    stage4_kernel<<<dim3(NDIM / 64, BSZ / 64, 2), blk>>>(Wk1);
    stage5_kernel<<<dim3(BSZ), blk>>>(out);
}

// round 2
// speedup vs baseline: 2.9666x; 2.9666x over previous
#include <cuda_runtime.h>
#include <math.h>

#define BSZ  128
#define NDIM 256
#define HDIM 1024

#define ALPHA 60.0f
#define BETA  20.0f
#define EPSC  1e-8f

// ---- scratch (allocation-free: __device__ globals) ----
__device__ float g_H [3][BSZ * HDIM];       // tanh hidden for f,g,k
__device__ float g_D [BSZ * HDIM];          // 1 - Hk^2
__device__ float g_f [BSZ * NDIM];
__device__ float g_g [BSZ * NDIM];
__device__ float g_k [BSZ * NDIM];
__device__ float g_dv[2][BSZ * HDIM];       // D * (Wk2^T {f,g})

// split-K partials
__device__ float g_p1[3][2][BSZ * HDIM];    // stage1: K=256 split 2
__device__ float g_p2[3][8][BSZ * NDIM];    // stage2: K=1024 split 8
__device__ float g_p3[2][2][BSZ * HDIM];    // stage3: K=256 split 2
__device__ float g_p4[2][8][BSZ * NDIM];    // stage4: K=1024 split 8

// ============================================================
// Core tile GEMM: 64x64 output tile, BK=16, 256 threads, 4x4/thread.
// BT=true : C[m,n] = sum_k A[m*lda+k] * B[n*ldb+k]   (NT)
// BT=false: C[m,n] = sum_k A[m*lda+k] * B[k*ldb+n]   (NN)
// Pointers pre-offset for the K-chunk; K is the chunk length.
// ============================================================
template <bool BT>
__device__ __forceinline__ void gemm_tile_64(
    const float* __restrict__ A, int lda,
    const float* __restrict__ B, int ldb,
    int K, int bm, int bn, float acc[4][4])
{
    constexpr int BK = 16;
    __shared__ float As[BK][64];
    __shared__ float Bs[BK][64];

    const int tid = threadIdx.x;
    const int tm = (tid >> 4) * 4;
    const int tn = (tid & 15) * 4;
    const int lr = tid >> 2;         // 0..63
    const int lc = (tid & 3) * 4;    // 0,4,8,12
    const int br = tid >> 4;         // 0..15
    const int bc = (tid & 15) * 4;   // 0..60

    for (int k0 = 0; k0 < K; k0 += BK) {
        float4 av = *reinterpret_cast<const float4*>(&A[(size_t)(bm + lr) * lda + k0 + lc]);
        As[lc + 0][lr] = av.x;
        As[lc + 1][lr] = av.y;
        As[lc + 2][lr] = av.z;
        As[lc + 3][lr] = av.w;
        if (BT) {
            float4 bv = *reinterpret_cast<const float4*>(&B[(size_t)(bn + lr) * ldb + k0 + lc]);
            Bs[lc + 0][lr] = bv.x;
            Bs[lc + 1][lr] = bv.y;
            Bs[lc + 2][lr] = bv.z;
            Bs[lc + 3][lr] = bv.w;
        } else {
            float4 bv = *reinterpret_cast<const float4*>(&B[(size_t)(k0 + br) * ldb + bn + bc]);
            *reinterpret_cast<float4*>(&Bs[br][bc]) = bv;
        }
        __syncthreads();
#pragma unroll
        for (int kk = 0; kk < BK; kk++) {
            float4 a4 = *reinterpret_cast<const float4*>(&As[kk][tm]);
            float4 b4 = *reinterpret_cast<const float4*>(&Bs[kk][tn]);
            float aa[4] = {a4.x, a4.y, a4.z, a4.w};
            float bb[4] = {b4.x, b4.y, b4.z, b4.w};
#pragma unroll
            for (int i = 0; i < 4; i++)
#pragma unroll
                for (int j = 0; j < 4; j++)
                    acc[i][j] = fmaf(aa[i], bb[j], acc[i][j]);
        }
        __syncthreads();
    }
}

__device__ __forceinline__ void store_acc(float* __restrict__ out, int ld,
                                          int bm, int bn, float acc[4][4])
{
    const int tid = threadIdx.x;
    const int tm = (tid >> 4) * 4, tn = (tid & 15) * 4;
#pragma unroll
    for (int i = 0; i < 4; i++) {
        float4 v = make_float4(acc[i][0], acc[i][1], acc[i][2], acc[i][3]);
        *reinterpret_cast<float4*>(&out[(size_t)(bm + tm + i) * ld + bn + tn]) = v;
    }
}

// ============================================================
// Stage 1 GEMM partials: p1[z][s] = x[:, s*128:(s+1)*128] @ W1[z][:, chunk]^T
// grid (16, 2, 6)
// ============================================================
__global__ __launch_bounds__(256) void s1_kernel(
    const float* __restrict__ x,
    const float* __restrict__ Wf1, const float* __restrict__ Wg1,
    const float* __restrict__ Wk1)
{
    const int zs = blockIdx.z, z = zs >> 1, s = zs & 1;
    const float* W = (z == 0) ? Wf1 : (z == 1) ? Wg1 : Wk1;
    const int koff = s * 128;
    float acc[4][4] = {};
    gemm_tile_64<true>(x + koff, NDIM, W + koff, NDIM, 128,
                       blockIdx.y * 64, blockIdx.x * 64, acc);
    store_acc(g_p1[z][s], HDIM, blockIdx.y * 64, blockIdx.x * 64, acc);
}

// Reduce 1: H[z] = tanh(p1[z][0]+p1[z][1]+b1);  D = 1-Hk^2.  grid (128, 3)
__global__ __launch_bounds__(256) void r1_kernel(
    const float* __restrict__ bf1, const float* __restrict__ bg1,
    const float* __restrict__ bk1)
{
    const int z = blockIdx.y;
    const float* bias = (z == 0) ? bf1 : (z == 1) ? bg1 : bk1;
    const int i4 = blockIdx.x * 256 + threadIdx.x;          // float4 index
    const int col4 = i4 & (HDIM / 4 - 1);
    float4 a = reinterpret_cast<const float4*>(g_p1[z][0])[i4];
    float4 b = reinterpret_cast<const float4*>(g_p1[z][1])[i4];
    float4 bs = reinterpret_cast<const float4*>(bias)[col4];
    float4 h;
    h.x = tanhf(a.x + b.x + bs.x);
    h.y = tanhf(a.y + b.y + bs.y);
    h.z = tanhf(a.z + b.z + bs.z);
    h.w = tanhf(a.w + b.w + bs.w);
    reinterpret_cast<float4*>(g_H[z])[i4] = h;
    if (z == 2) {
        float4 d;
        d.x = 1.0f - h.x * h.x; d.y = 1.0f - h.y * h.y;
        d.z = 1.0f - h.z * h.z; d.w = 1.0f - h.w * h.w;
        reinterpret_cast<float4*>(g_D)[i4] = d;
    }
}

// ============================================================
// Stage 2 GEMM partials: p2[z][s] = H[z][:, chunk] @ W2[z][:, chunk]^T
// grid (4, 2, 24)
// ============================================================
__global__ __launch_bounds__(256) void s2_kernel(
    const float* __restrict__ Wf2, const float* __restrict__ Wg2,
    const float* __restrict__ Wk2)
{
    const int zs = blockIdx.z, z = zs >> 3, s = zs & 7;
    const float* W = (z == 0) ? Wf2 : (z == 1) ? Wg2 : Wk2;
    const int koff = s * 128;
    float acc[4][4] = {};
    gemm_tile_64<true>(g_H[z] + koff, HDIM, W + koff, HDIM, 128,
                       blockIdx.y * 64, blockIdx.x * 64, acc);
    store_acc(g_p2[z][s], NDIM, blockIdx.y * 64, blockIdx.x * 64, acc);
}

// Reduce 2: {f,g,k} = sum_s p2[z][s] + b2.  grid (32, 3)
__global__ __launch_bounds__(256) void r2_kernel(
    const float* __restrict__ bf2, const float* __restrict__ bg2,
    const float* __restrict__ bk2)
{
    const int z = blockIdx.y;
    const float* bias = (z == 0) ? bf2 : (z == 1) ? bg2 : bk2;
    float* out = (z == 0) ? g_f : (z == 1) ? g_g : g_k;
    const int i4 = blockIdx.x * 256 + threadIdx.x;
    const int col4 = i4 & (NDIM / 4 - 1);
    float4 acc = reinterpret_cast<const float4*>(bias)[col4];
#pragma unroll
    for (int s = 0; s < 8; s++) {
        float4 p = reinterpret_cast<const float4*>(g_p2[z][s])[i4];
        acc.x += p.x; acc.y += p.y; acc.z += p.z; acc.w += p.w;
    }
    reinterpret_cast<float4*>(out)[i4] = acc;
}

// ============================================================
// Stage 3 GEMM partials (NN): p3[z][s] = {f,g}[:, chunk] @ Wk2[chunk, :]
// grid (16, 2, 4)
// ============================================================
__global__ __launch_bounds__(256) void s3_kernel(const float* __restrict__ Wk2)
{
    const int zs = blockIdx.z, z = zs >> 1, s = zs & 1;
    const float* A = ((z == 0) ? g_f : g_g) + s * 128;
    const float* B = Wk2 + (size_t)s * 128 * HDIM;
    float acc[4][4] = {};
    gemm_tile_64<false>(A, NDIM, B, HDIM, 128,
                        blockIdx.y * 64, blockIdx.x * 64, acc);
    store_acc(g_p3[z][s], HDIM, blockIdx.y * 64, blockIdx.x * 64, acc);
}

// Reduce 3: dv[z] = (p3[z][0]+p3[z][1]) * D.  grid (128, 2)
__global__ __launch_bounds__(256) void r3_kernel()
{
    const int z = blockIdx.y;
    const int i4 = blockIdx.x * 256 + threadIdx.x;
    float4 a = reinterpret_cast<const float4*>(g_p3[z][0])[i4];
    float4 b = reinterpret_cast<const float4*>(g_p3[z][1])[i4];
    float4 d = reinterpret_cast<const float4*>(g_D)[i4];
    float4 o;
    o.x = (a.x + b.x) * d.x; o.y = (a.y + b.y) * d.y;
    o.z = (a.z + b.z) * d.z; o.w = (a.w + b.w) * d.w;
    reinterpret_cast<float4*>(g_dv[z])[i4] = o;
}

// ============================================================
// Stage 4 GEMM partials (NN): p4[z][s] = dv[z][:, chunk] @ Wk1[chunk, :]
// grid (4, 2, 16)
// ============================================================
__global__ __launch_bounds__(256) void s4_kernel(const float* __restrict__ Wk1)
{
    const int zs = blockIdx.z, z = zs >> 3, s = zs & 7;
    const float* A = g_dv[z] + s * 128;
    const float* B = Wk1 + (size_t)s * 128 * NDIM;
    float acc[4][4] = {};
    gemm_tile_64<false>(A, HDIM, B, NDIM, 128,
                        blockIdx.y * 64, blockIdx.x * 64, acc);
    store_acc(g_p4[z][s], NDIM, blockIdx.y * 64, blockIdx.x * 64, acc);
}

// ============================================================
// Stage 5: fuse stage-4 reduce + norms + mask + output. 1 block/row.
// ============================================================
__global__ __launch_bounds__(256) void s5_kernel(float* __restrict__ out)
{
    const int b = blockIdx.x;
    const int i = threadIdx.x;
    const int idx = b * NDIM + i;

    float jfv = 0.f, jgv = 0.f;
#pragma unroll
    for (int s = 0; s < 8; s++) {
        jfv += g_p4[0][s][idx];
        jgv += g_p4[1][s][idx];
    }
    const float kv = g_k[idx];

    float kn2 = kv * kv;
    float jf2 = jfv * jfv;
    float dt  = kv * jgv;

#pragma unroll
    for (int off = 16; off > 0; off >>= 1) {
        kn2 += __shfl_down_sync(0xffffffffu, kn2, off);
        jf2 += __shfl_down_sync(0xffffffffu, jf2, off);
        dt  += __shfl_down_sync(0xffffffffu, dt,  off);
    }

    __shared__ float s_kn2[8], s_jf2[8], s_dt[8];
    __shared__ float s_scale;
    const int warp = i >> 5, lane = i & 31;
    if (lane == 0) { s_kn2[warp] = kn2; s_jf2[warp] = jf2; s_dt[warp] = dt; }
    __syncthreads();

    if (i == 0) {
        float tkn2 = 0.f, tjf2 = 0.f, tdt = 0.f;
#pragma unroll
        for (int w = 0; w < 8; w++) { tkn2 += s_kn2[w]; tjf2 += s_jf2[w]; tdt += s_dt[w]; }
        float kn   = sqrtf(tkn2);
        float kn9  = tkn2 * tkn2 * tkn2 * tkn2 * kn;
        float kn10 = kn9 * kn;
        float c1 = sqrtf(tjf2) - ALPHA * kn9;
        float c2 = tdt - BETA * kn10;
        bool mask = (c1 > EPSC) || (c2 < -EPSC);
        s_scale = mask ? 0.5f : 1.0f;
    }
    __syncthreads();

    out[idx] = s_scale * (g_f[idx] + g_g[idx]);
}

// ============================================================
// inputs: 0:t 1:x 2:Wf1 3:bf1 4:Wf2 5:bf2 6:Wg1 7:bg1 8:Wg2 9:bg2
//         10:Wk1 11:bk1 12:Wk2 13:bk2
// ============================================================
extern "C" void kernel_launch(void* const* d_in, const int* in_sizes, int n_in,
                              void* d_out, int out_size)
{
    const float* x   = (const float*)d_in[1];
    const float* Wf1 = (const float*)d_in[2];
    const float* bf1 = (const float*)d_in[3];
    const float* Wf2 = (const float*)d_in[4];
    const float* bf2 = (const float*)d_in[5];
    const float* Wg1 = (const float*)d_in[6];
    const float* bg1 = (const float*)d_in[7];
    const float* Wg2 = (const float*)d_in[8];
    const float* bg2 = (const float*)d_in[9];
    const float* Wk1 = (const float*)d_in[10];
    const float* bk1 = (const float*)d_in[11];
    const float* Wk2 = (const float*)d_in[12];
    const float* bk2 = (const float*)d_in[13];
    float* out = (float*)d_out;

    dim3 blk(256);
    s1_kernel<<<dim3(HDIM / 64, BSZ / 64, 6), blk>>>(x, Wf1, Wg1, Wk1);
    r1_kernel<<<dim3(BSZ * HDIM / 1024, 3), blk>>>(bf1, bg1, bk1);
    s2_kernel<<<dim3(NDIM / 64, BSZ / 64, 24), blk>>>(Wf2, Wg2, Wk2);
    r2_kernel<<<dim3(BSZ * NDIM / 1024, 3), blk>>>(bf2, bg2, bk2);
    s3_kernel<<<dim3(HDIM / 64, BSZ / 64, 4), blk>>>(Wk2);
    r3_kernel<<<dim3(BSZ * HDIM / 1024, 2), blk>>>();
    s4_kernel<<<dim3(NDIM / 64, BSZ / 64, 16), blk>>>(Wk1);
    s5_kernel<<<dim3(BSZ), blk>>>(out);
}